// round 1
// baseline (speedup 1.0000x reference)
#include <cuda_runtime.h>

// ---------------------------------------------------------------------------
// CustomizingAttention: location-sensitive multi-head attention
//   B=32, QLEN=128, VLEN=2048, HIDDEN=1024, HEADS=8, DIM=128, CONV_C=10
// Outputs (concatenated in d_out):
//   out  [32,128,1024]        = 4,194,304 floats
//   attn [256,128,2048]       = 67,108,864 floats
// ---------------------------------------------------------------------------

#define ULL unsigned long long

static const int B_   = 32;
static const int QL   = 128;
static const int VL   = 2048;
static const int HID  = 1024;
static const int HDS  = 8;
static const int DIM_ = 128;

// Scratch (device globals; no runtime allocation allowed)
__device__ float g_qh[4194304];    // [H*B, QL, DIM]   head-major
__device__ float g_vh[67108864];   // [H*B, VL, DIM]   head-major
__device__ float g_A0[128], g_A1[128], g_A2[128], g_Cc[128];

// ---------------------------------------------------------------------------
// f32x2 packed helpers (FFMA2; ptxas emits only from PTX per sm_103a docs)
// ---------------------------------------------------------------------------
__device__ __forceinline__ ULL fma2(ULL a, ULL b, ULL c) {
    ULL d;
    asm("fma.rn.f32x2 %0, %1, %2, %3;" : "=l"(d) : "l"(a), "l"(b), "l"(c));
    return d;
}
__device__ __forceinline__ ULL dup2(float a) {
    ULL r;
    asm("mov.b64 %0, {%1, %1};" : "=l"(r) : "f"(a));
    return r;
}
__device__ __forceinline__ void unpack2(ULL v, float& lo, float& hi) {
    asm("mov.b64 {%0, %1}, %2;" : "=f"(lo), "=f"(hi) : "l"(v));
}

// ---------------------------------------------------------------------------
// Core GEMM mainloop: C[128,128] block tile, BK=8, 256 threads, 8x8/thread.
// A is [M,K] row-major (K-contiguous). B either [N,K] (TN) or [K,N] (NN).
// Accumulators are f32x2 pairs: acc[i][jj] holds cols (2jj, 2jj+1) of strip.
// ---------------------------------------------------------------------------
template <bool B_KMAJOR>
__device__ __forceinline__ void gemm_core(
    const float* __restrict__ A, int lda,
    const float* __restrict__ Bm, int ldb,
    int K,
    ULL (&acc)[8][4],
    float (&sA)[8][132], float (&sB)[8][132])
{
    const int t  = threadIdx.x;
    const int am = t >> 1;                 // 0..127
    const int ak = (t & 1) * 4;            // 0 or 4
    const int bk = t >> 5;                 // 0..7   (NN loader)
    const int bn = (t & 31) * 4;           // 0..124 (NN loader)
    const int tm = (t & 15) * 4;
    const int tn = (t >> 4) * 4;

#pragma unroll
    for (int i = 0; i < 8; i++)
#pragma unroll
        for (int jj = 0; jj < 4; jj++) acc[i][jj] = 0ull;

    // prefetch first tile into registers
    float4 av = *(const float4*)(A + (size_t)am * lda + ak);
    float4 bv;
    if (B_KMAJOR) bv = *(const float4*)(Bm + (size_t)am * ldb + ak);
    else          bv = *(const float4*)(Bm + (size_t)bk * ldb + bn);

    for (int k0 = 0; k0 < K; k0 += 8) {
        __syncthreads();
        sA[ak + 0][am] = av.x; sA[ak + 1][am] = av.y;
        sA[ak + 2][am] = av.z; sA[ak + 3][am] = av.w;
        if (B_KMAJOR) {
            sB[ak + 0][am] = bv.x; sB[ak + 1][am] = bv.y;
            sB[ak + 2][am] = bv.z; sB[ak + 3][am] = bv.w;
        } else {
            *(float4*)&sB[bk][bn] = bv;
        }
        __syncthreads();

        if (k0 + 8 < K) {   // prefetch next tile (overlaps compute below)
            av = *(const float4*)(A + (size_t)am * lda + (k0 + 8) + ak);
            if (B_KMAJOR) bv = *(const float4*)(Bm + (size_t)am * ldb + (k0 + 8) + ak);
            else          bv = *(const float4*)(Bm + (size_t)(k0 + 8 + bk) * ldb + bn);
        }

#pragma unroll
        for (int k = 0; k < 8; k++) {
            float4 aA = *(const float4*)&sA[k][tm];
            float4 aB = *(const float4*)&sA[k][tm + 64];
            ULL ad[8];
            ad[0] = dup2(aA.x); ad[1] = dup2(aA.y); ad[2] = dup2(aA.z); ad[3] = dup2(aA.w);
            ad[4] = dup2(aB.x); ad[5] = dup2(aB.y); ad[6] = dup2(aB.z); ad[7] = dup2(aB.w);
            ULL bp[4];
            bp[0] = *(const ULL*)&sB[k][tn];
            bp[1] = *(const ULL*)&sB[k][tn + 2];
            bp[2] = *(const ULL*)&sB[k][tn + 64];
            bp[3] = *(const ULL*)&sB[k][tn + 66];
#pragma unroll
            for (int i = 0; i < 8; i++)
#pragma unroll
                for (int jj = 0; jj < 4; jj++)
                    acc[i][jj] = fma2(ad[i], bp[jj], acc[i][jj]);
        }
    }
}

__device__ __forceinline__ int row_of(int tm, int i) { return (i < 4) ? tm + i : tm + 64 + (i - 4); }
__device__ __forceinline__ int col_of(int tn, int jj) { return (jj < 2) ? tn + 2 * jj : tn + 64 + 2 * (jj - 2); }

// ---------------------------------------------------------------------------
// Precompute loc-energy coefficients: A_t[d] = sum_c Wloc[d,c]*conv_w[c,0,t]
// ---------------------------------------------------------------------------
__global__ void prep_kernel(const float* __restrict__ conv_w,
                            const float* __restrict__ conv_b,
                            const float* __restrict__ Wloc)
{
    int d = threadIdx.x;   // 128 threads
    float a0 = 0.f, a1 = 0.f, a2 = 0.f, c = 0.f;
#pragma unroll
    for (int cc = 0; cc < 10; cc++) {
        float wl = Wloc[d * 10 + cc];
        a0 += wl * conv_w[cc * 3 + 0];
        a1 += wl * conv_w[cc * 3 + 1];
        a2 += wl * conv_w[cc * 3 + 2];
        c  += wl * conv_b[cc];
    }
    g_A0[d] = a0; g_A1[d] = a1; g_A2[d] = a2; g_Cc[d] = c;
}

// ---------------------------------------------------------------------------
// qp = q @ Wq^T + bq  -> g_qh head-major   grid (8 n-tiles, 32 m-tiles)
// ---------------------------------------------------------------------------
__global__ __launch_bounds__(256) void gemm_qp_kernel(
    const float* __restrict__ q, const float* __restrict__ Wq,
    const float* __restrict__ bq)
{
    __shared__ float sA[8][132], sB[8][132];
    ULL acc[8][4];
    const int n0 = blockIdx.x * 128;
    const int m0 = blockIdx.y * 128;
    gemm_core<true>(q + (size_t)m0 * HID, HID, Wq + (size_t)n0 * HID, HID, HID, acc, sA, sB);

    const int t = threadIdx.x;
    const int tm = (t & 15) * 4, tn = (t >> 4) * 4;
    const int h = blockIdx.x;               // n0 = h*128
#pragma unroll
    for (int i = 0; i < 8; i++) {
        int row = row_of(tm, i);
        int m = m0 + row;
        int b = m >> 7, qpos = m & 127;
        float* dst = &g_qh[(((size_t)(h * B_ + b)) * QL + qpos) * DIM_];
#pragma unroll
        for (int jj = 0; jj < 4; jj++) {
            int col = col_of(tn, jj);
            float lo, hi; unpack2(acc[i][jj], lo, hi);
            dst[col]     = lo + bq[n0 + col];
            dst[col + 1] = hi + bq[n0 + col + 1];
        }
    }
}

// ---------------------------------------------------------------------------
// vp = v @ Wv^T + bias + loc_energy -> g_vh head-major  grid (8, 512)
// ---------------------------------------------------------------------------
__global__ __launch_bounds__(256) void gemm_vp_kernel(
    const float* __restrict__ v, const float* __restrict__ Wv,
    const float* __restrict__ bias, const float* __restrict__ la)
{
    __shared__ float sA[8][132], sB[8][132];
    ULL acc[8][4];
    const int n0 = blockIdx.x * 128;
    const int m0 = blockIdx.y * 128;
    gemm_core<true>(v + (size_t)m0 * HID, HID, Wv + (size_t)n0 * HID, HID, HID, acc, sA, sB);

    const int t = threadIdx.x;
    const int tm = (t & 15) * 4, tn = (t >> 4) * 4;
    const int h = blockIdx.x;
#pragma unroll
    for (int i = 0; i < 8; i++) {
        int row = row_of(tm, i);
        int m = m0 + row;
        int b = m >> 11, vpos = m & 2047;
        const float* lar = la + ((size_t)(b * HDS + h)) * VL;
        float lm1 = (vpos > 0)      ? lar[vpos - 1] : 0.f;
        float l0  =                   lar[vpos];
        float lp1 = (vpos < VL - 1) ? lar[vpos + 1] : 0.f;
        float* dst = &g_vh[(((size_t)(h * B_ + b)) * VL + vpos) * DIM_];
#pragma unroll
        for (int jj = 0; jj < 4; jj++) {
            int col = col_of(tn, jj);       // col == d (0..127)
            float lo, hi; unpack2(acc[i][jj], lo, hi);
            float add0 = bias[n0 + col]     + g_Cc[col]     + g_A0[col]     * lm1 + g_A1[col]     * l0 + g_A2[col]     * lp1;
            float add1 = bias[n0 + col + 1] + g_Cc[col + 1] + g_A0[col + 1] * lm1 + g_A1[col + 1] * l0 + g_A2[col + 1] * lp1;
            dst[col]     = lo + add0;
            dst[col + 1] = hi + add1;
        }
    }
}

// ---------------------------------------------------------------------------
// score (raw) = qh @ vh^T / sqrt(D) -> attn region    grid (16 v-tiles, 256 n)
// ---------------------------------------------------------------------------
__global__ __launch_bounds__(256) void gemm_score_kernel(float* __restrict__ attn)
{
    __shared__ float sA[8][132], sB[8][132];
    ULL acc[8][4];
    const int nb = blockIdx.y;
    const int n0 = blockIdx.x * 128;
    gemm_core<true>(g_qh + (size_t)nb * QL * DIM_, DIM_,
                    g_vh + (size_t)nb * VL * DIM_ + (size_t)n0 * DIM_, DIM_,
                    DIM_, acc, sA, sB);

    const float sc = 0.08838834764831845f;  // 1/sqrt(128)
    const int t = threadIdx.x;
    const int tm = (t & 15) * 4, tn = (t >> 4) * 4;
#pragma unroll
    for (int i = 0; i < 8; i++) {
        int row = row_of(tm, i);
        size_t base = ((size_t)nb * QL + row) * VL;
#pragma unroll
        for (int jj = 0; jj < 4; jj++) {
            int col = col_of(tn, jj);
            float lo, hi; unpack2(acc[i][jj], lo, hi);
            attn[base + n0 + col]     = lo * sc;
            attn[base + n0 + col + 1] = hi * sc;
        }
    }
}

// ---------------------------------------------------------------------------
// softmax in place over last dim (2048). One block per (n,q) row.
// ---------------------------------------------------------------------------
__global__ __launch_bounds__(256) void softmax_kernel(float* __restrict__ attn)
{
    __shared__ float red[256];
    const size_t base = (size_t)blockIdx.x * VL;
    const int t = threadIdx.x;
    float x[8];
    float mx = -1e30f;
#pragma unroll
    for (int i = 0; i < 8; i++) { x[i] = attn[base + t + 256 * i]; mx = fmaxf(mx, x[i]); }
    red[t] = mx; __syncthreads();
    for (int s = 128; s > 0; s >>= 1) { if (t < s) red[t] = fmaxf(red[t], red[t + s]); __syncthreads(); }
    mx = red[0];
    __syncthreads();
    float sum = 0.f;
#pragma unroll
    for (int i = 0; i < 8; i++) { x[i] = __expf(x[i] - mx); sum += x[i]; }
    red[t] = sum; __syncthreads();
    for (int s = 128; s > 0; s >>= 1) { if (t < s) red[t] += red[t + s]; __syncthreads(); }
    float inv = 1.0f / red[0];
#pragma unroll
    for (int i = 0; i < 8; i++) attn[base + t + 256 * i] = x[i] * inv;
}

// ---------------------------------------------------------------------------
// out = attn @ vh (NN GEMM, K=2048), scatter to (b,q,h*D+d). grid (256)
// ---------------------------------------------------------------------------
__global__ __launch_bounds__(256) void gemm_out_kernel(
    const float* __restrict__ attn, float* __restrict__ out)
{
    __shared__ float sA[8][132], sB[8][132];
    ULL acc[8][4];
    const int nb = blockIdx.x;
    gemm_core<false>(attn + (size_t)nb * QL * VL, VL,
                     g_vh + (size_t)nb * VL * DIM_, DIM_,
                     VL, acc, sA, sB);

    const int t = threadIdx.x;
    const int tm = (t & 15) * 4, tn = (t >> 4) * 4;
    const int h = nb >> 5, b = nb & 31;
#pragma unroll
    for (int i = 0; i < 8; i++) {
        int row = row_of(tm, i);   // q
        float* dst = &out[((size_t)(b * QL + row)) * HID + h * DIM_];
#pragma unroll
        for (int jj = 0; jj < 4; jj++) {
            int col = col_of(tn, jj);  // d
            float lo, hi; unpack2(acc[i][jj], lo, hi);
            dst[col]     = lo;
            dst[col + 1] = hi;
        }
    }
}

// ---------------------------------------------------------------------------
extern "C" void kernel_launch(void* const* d_in, const int* in_sizes, int n_in,
                              void* d_out, int out_size)
{
    const float* q         = (const float*)d_in[0];
    const float* v         = (const float*)d_in[1];
    const float* last_attn = (const float*)d_in[2];
    const float* conv_w    = (const float*)d_in[3];
    const float* conv_b    = (const float*)d_in[4];
    const float* Wq        = (const float*)d_in[5];
    const float* bq        = (const float*)d_in[6];
    const float* Wv        = (const float*)d_in[7];
    const float* Wloc      = (const float*)d_in[8];
    const float* bias      = (const float*)d_in[9];

    float* out  = (float*)d_out;
    float* attn = out + 4194304;   // out is [32,128,1024] -> 4,194,304 floats

    prep_kernel<<<1, 128>>>(conv_w, conv_b, Wloc);
    gemm_qp_kernel<<<dim3(8, 32), 256>>>(q, Wq, bq);
    gemm_vp_kernel<<<dim3(8, 512), 256>>>(v, Wv, bias, last_attn);
    gemm_score_kernel<<<dim3(16, 256), 256>>>(attn);
    softmax_kernel<<<32768, 256>>>(attn);
    gemm_out_kernel<<<256, 256>>>(attn, out);
}

// round 3
// speedup vs baseline: 1.7542x; 1.7542x over previous
#include <cuda_runtime.h>
#include <cstdint>

#define DI __device__ __forceinline__

static const int QL  = 128;
static const int VL  = 2048;
static const int HID = 1024;

// Scratch (device globals; no runtime allocation allowed)
__device__ float g_qh[4194304];    // [H*B, QL, DIM]
__device__ float g_vh[67108864];   // [H*B, VL, DIM]
__device__ float g_A0[128], g_A1[128], g_A2[128], g_Cc[128];

// ---------------------------------------------------------------------------
DI uint32_t smem_u32(const void* p) {
    uint32_t a;
    asm("{ .reg .u64 t; cvta.to.shared.u64 t, %1; cvt.u32.u64 %0, t; }" : "=r"(a) : "l"(p));
    return a;
}

// pack two floats to bf16x2 (lo element in bits[15:0])
DI uint32_t pack2(float lo, float hi) {
    uint32_t r;
    asm("cvt.rn.bf16x2.f32 %0, %1, %2;" : "=r"(r) : "f"(hi), "f"(lo));
    return r;
}
// split (a,b) into bf16 hi pair (returned) and bf16 lo pair (out param)
DI uint32_t sp2(float a, float b, uint32_t& lo) {
    uint32_t h = pack2(a, b);
    float ha = __uint_as_float(h << 16);
    float hb = __uint_as_float(h & 0xffff0000u);
    lo = pack2(a - ha, b - hb);
    return h;
}

DI void ldm4(uint32_t* r, uint32_t a) {
    asm volatile("ldmatrix.sync.aligned.m8n8.x4.shared.b16 {%0,%1,%2,%3}, [%4];"
        : "=r"(r[0]), "=r"(r[1]), "=r"(r[2]), "=r"(r[3]) : "r"(a));
}

DI void mma16816(float* d, const uint32_t* a, uint32_t b0, uint32_t b1) {
    asm volatile("mma.sync.aligned.m16n8k16.row.col.f32.bf16.bf16.f32 "
        "{%0,%1,%2,%3},{%4,%5,%6,%7},{%8,%9},{%0,%1,%2,%3};"
        : "+f"(d[0]), "+f"(d[1]), "+f"(d[2]), "+f"(d[3])
        : "r"(a[0]), "r"(a[1]), "r"(a[2]), "r"(a[3]), "r"(b0), "r"(b1));
}

// ---------------------------------------------------------------------------
// smem layout: 4 tiles of [128 rows][80 bytes] (32 bf16 + pad):
//   A_hi @0, A_lo @10240, B_hi @20480, B_lo @30720     (total 40960 <= 48K)
// Row r, k-slot s (8 bf16) at r*80 + s*16. 80B pitch -> conflict-free ldmatrix.
// ---------------------------------------------------------------------------
static const int T_AL = 10240, T_BH = 20480, T_BL = 30720;
static const int SMEM_SZ = 40960;

// MODE 0: qp = q@Wq^T + bq           -> g_qh    grid(8, 32)
// MODE 1: vp = v@Wv^T + bias + loc   -> g_vh    grid(8, 512)
// MODE 2: score = qh@vh^T * sc       -> attn    grid(16, 256)
// MODE 3: out = attn@vh              -> out     grid(256)
template <int MODE>
__global__ void __launch_bounds__(256)
mma_gemm(const float* __restrict__ Ain, const float* __restrict__ Bin,
         const float* __restrict__ biasv, const float* __restrict__ la,
         float* __restrict__ dsto)
{
    extern __shared__ char sm[];
    const uint32_t smb = smem_u32(sm);
    const int t = threadIdx.x, lane = t & 31, w = t >> 5;

    constexpr int K  = (MODE < 2) ? HID : (MODE == 2 ? 128 : VL);
    constexpr int NC = K / 32;

    const float* A; const float* Bsrc; int lda, ldb;
    if (MODE <= 1) {
        A    = Ain + (size_t)blockIdx.y * 128 * HID;
        Bsrc = Bin + (size_t)blockIdx.x * 128 * HID;
        lda = ldb = HID;
    } else if (MODE == 2) {
        A    = g_qh + (size_t)blockIdx.y * QL * 128;
        Bsrc = g_vh + (size_t)blockIdx.y * VL * 128 + (size_t)blockIdx.x * 128 * 128;
        lda = ldb = 128;
    } else {
        A    = Ain + (size_t)blockIdx.x * QL * VL;
        Bsrc = g_vh + (size_t)blockIdx.x * VL * 128;
        lda = VL; ldb = 128;
    }

    const int arow = t >> 1, ahalf = t & 1;
    const float* ap = A + (size_t)arow * lda + ahalf * 16;
    const float* bp = (MODE == 3)
        ? Bsrc + (size_t)(t & 31) * 128 + (t >> 5) * 16
        : Bsrc + (size_t)arow * ldb + ahalf * 16;

    float4 ar[4], br[4];
#pragma unroll
    for (int j = 0; j < 4; j++) {
        ar[j] = *(const float4*)(ap + j * 4);
        br[j] = (MODE == 3) ? *(const float4*)(bp + j * 4)
                            : *(const float4*)(bp + j * 4);
    }

    float acc[2][8][4];
#pragma unroll
    for (int i = 0; i < 2; i++)
#pragma unroll
        for (int j = 0; j < 8; j++)
#pragma unroll
            for (int k = 0; k < 4; k++) acc[i][j][k] = 0.f;

    const int wm0 = (w & 3) * 32, wn0 = (w >> 2) * 64;

    for (int c = 0; c < NC; c++) {
        // ---- STS (convert fp32 -> bf16 hi/lo) ----
        {
            uint32_t off = arow * 80 + ahalf * 32;
            uint4 H, L;
            H.x = sp2(ar[0].x, ar[0].y, L.x); H.y = sp2(ar[0].z, ar[0].w, L.y);
            H.z = sp2(ar[1].x, ar[1].y, L.z); H.w = sp2(ar[1].z, ar[1].w, L.w);
            *(uint4*)(sm + off)        = H;
            *(uint4*)(sm + T_AL + off) = L;
            H.x = sp2(ar[2].x, ar[2].y, L.x); H.y = sp2(ar[2].z, ar[2].w, L.y);
            H.z = sp2(ar[3].x, ar[3].y, L.z); H.w = sp2(ar[3].z, ar[3].w, L.w);
            *(uint4*)(sm + off + 16)        = H;
            *(uint4*)(sm + T_AL + off + 16) = L;
        }
        if (MODE == 3) {
            // transpose: br holds vh[v][d0..d0+15]; scatter to rows d (k-major)
            const int v = t & 31, d0 = (t >> 5) * 16;
            const float* bf = (const float*)br;
            uint32_t ob = ((uint32_t)(v >> 3)) * 16 + (v & 7) * 2;
#pragma unroll
            for (int i = 0; i < 16; i++) {
                float aa = bf[i];
                uint16_t hb; asm("cvt.rn.bf16.f32 %0, %1;" : "=h"(hb) : "f"(aa));
                float hf = __uint_as_float(((uint32_t)hb) << 16);
                uint16_t lb; asm("cvt.rn.bf16.f32 %0, %1;" : "=h"(lb) : "f"(aa - hf));
                uint32_t o = (uint32_t)(d0 + i) * 80 + ob;
                *(uint16_t*)(sm + T_BH + o) = hb;
                *(uint16_t*)(sm + T_BL + o) = lb;
            }
        } else {
            uint32_t off = arow * 80 + ahalf * 32;
            uint4 H, L;
            H.x = sp2(br[0].x, br[0].y, L.x); H.y = sp2(br[0].z, br[0].w, L.y);
            H.z = sp2(br[1].x, br[1].y, L.z); H.w = sp2(br[1].z, br[1].w, L.w);
            *(uint4*)(sm + T_BH + off) = H;
            *(uint4*)(sm + T_BL + off) = L;
            H.x = sp2(br[2].x, br[2].y, L.x); H.y = sp2(br[2].z, br[2].w, L.y);
            H.z = sp2(br[3].x, br[3].y, L.z); H.w = sp2(br[3].z, br[3].w, L.w);
            *(uint4*)(sm + T_BH + off + 16) = H;
            *(uint4*)(sm + T_BL + off + 16) = L;
        }
        __syncthreads();

        // ---- prefetch next chunk while tensor cores chew ----
        if (c + 1 < NC) {
            const float* pa = ap + (c + 1) * 32;
#pragma unroll
            for (int j = 0; j < 4; j++) ar[j] = *(const float4*)(pa + j * 4);
            const float* pb = (MODE == 3) ? bp + (size_t)(c + 1) * 32 * 128
                                          : bp + (c + 1) * 32;
#pragma unroll
            for (int j = 0; j < 4; j++) br[j] = *(const float4*)(pb + j * 4);
        }

        // ---- compute: 2 k16 steps, 3 precision passes ----
#pragma unroll
        for (int ks = 0; ks < 2; ks++) {
            uint32_t aH[2][4], aL[2][4], bH[4][4], bL[4][4];
            const uint32_t rowsel = (uint32_t)(lane & 15) * 80
                                  + (uint32_t)((lane >> 4) + ks * 2) * 16;
#pragma unroll
            for (int mt = 0; mt < 2; mt++) {
                uint32_t ad = smb + (uint32_t)(wm0 + mt * 16) * 80 + rowsel;
                ldm4(aH[mt], ad);
                ldm4(aL[mt], ad + T_AL);
            }
#pragma unroll
            for (int g = 0; g < 4; g++) {
                uint32_t bd = smb + T_BH + (uint32_t)(wn0 + g * 16) * 80 + rowsel;
                ldm4(bH[g], bd);
                ldm4(bL[g], bd + (T_BL - T_BH));
            }
#pragma unroll
            for (int mt = 0; mt < 2; mt++)
#pragma unroll
                for (int g = 0; g < 4; g++) {
                    mma16816(acc[mt][2 * g],     aH[mt], bH[g][0], bH[g][2]);
                    mma16816(acc[mt][2 * g + 1], aH[mt], bH[g][1], bH[g][3]);
                }
#pragma unroll
            for (int mt = 0; mt < 2; mt++)
#pragma unroll
                for (int g = 0; g < 4; g++) {
                    mma16816(acc[mt][2 * g],     aH[mt], bL[g][0], bL[g][2]);
                    mma16816(acc[mt][2 * g + 1], aH[mt], bL[g][1], bL[g][3]);
                }
#pragma unroll
            for (int mt = 0; mt < 2; mt++)
#pragma unroll
                for (int g = 0; g < 4; g++) {
                    mma16816(acc[mt][2 * g],     aL[mt], bH[g][0], bH[g][2]);
                    mma16816(acc[mt][2 * g + 1], aL[mt], bH[g][1], bH[g][3]);
                }
        }
        __syncthreads();
    }

    // ---- epilogue: stage per-column vectors in (now free) smem ----
    float* stage = (float*)sm;
    if (MODE == 0) {
        if (t < 128) stage[t] = biasv[blockIdx.x * 128 + t];
    }
    if (MODE == 1) {
        if (t < 128) {
            stage[t]       = biasv[blockIdx.x * 128 + t] + g_Cc[t];
            stage[128 + t] = g_A0[t];
            stage[256 + t] = g_A1[t];
            stage[384 + t] = g_A2[t];
        }
        const int b = blockIdx.y >> 4, h = blockIdx.x;
        const int vpos0 = (blockIdx.y & 15) * 128;
        const float* lar = la + (size_t)(b * 8 + h) * VL;
        if (t < 130) {
            int g = vpos0 - 1 + t;
            stage[512 + t] = (g >= 0 && g < VL) ? lar[g] : 0.f;
        }
    }
    __syncthreads();

#pragma unroll
    for (int mt = 0; mt < 2; mt++) {
#pragma unroll
        for (int h2 = 0; h2 < 2; h2++) {
            const int row = wm0 + mt * 16 + (lane >> 2) + h2 * 8;
            float* dst;
            float lm1 = 0.f, l0 = 0.f, lp1 = 0.f;
            if (MODE == 0) {
                int b = blockIdx.y, h = blockIdx.x;
                dst = g_qh + (((size_t)(h * 32 + b)) * QL + row) * 128;
            } else if (MODE == 1) {
                int b = blockIdx.y >> 4, h = blockIdx.x;
                int vpos0 = (blockIdx.y & 15) * 128;
                lm1 = stage[512 + row];
                l0  = stage[512 + row + 1];
                lp1 = stage[512 + row + 2];
                dst = g_vh + (((size_t)(h * 32 + b)) * VL + vpos0 + row) * 128;
            } else if (MODE == 2) {
                dst = dsto + ((size_t)blockIdx.y * QL + row) * VL + blockIdx.x * 128;
            } else {
                int h = blockIdx.x >> 5, b = blockIdx.x & 31;
                dst = dsto + ((size_t)(b * QL + row)) * HID + h * 128;
            }
#pragma unroll
            for (int nt = 0; nt < 8; nt++) {
                const int col = wn0 + nt * 8 + 2 * (lane & 3);
                float x = acc[mt][nt][2 * h2];
                float y = acc[mt][nt][2 * h2 + 1];
                if (MODE == 0) {
                    x += stage[col]; y += stage[col + 1];
                } else if (MODE == 1) {
                    x += stage[col]     + stage[128 + col]     * lm1 + stage[256 + col]     * l0 + stage[384 + col]     * lp1;
                    y += stage[col + 1] + stage[128 + col + 1] * lm1 + stage[256 + col + 1] * l0 + stage[384 + col + 1] * lp1;
                } else if (MODE == 2) {
                    const float sc = 0.08838834764831845f;
                    x *= sc; y *= sc;
                }
                *(float2*)(dst + col) = make_float2(x, y);
            }
        }
    }
}

// ---------------------------------------------------------------------------
__global__ void prep_kernel(const float* __restrict__ conv_w,
                            const float* __restrict__ conv_b,
                            const float* __restrict__ Wloc)
{
    int d = threadIdx.x;
    float a0 = 0.f, a1 = 0.f, a2 = 0.f, c = 0.f;
#pragma unroll
    for (int cc = 0; cc < 10; cc++) {
        float wl = Wloc[d * 10 + cc];
        a0 += wl * conv_w[cc * 3 + 0];
        a1 += wl * conv_w[cc * 3 + 1];
        a2 += wl * conv_w[cc * 3 + 2];
        c  += wl * conv_b[cc];
    }
    g_A0[d] = a0; g_A1[d] = a1; g_A2[d] = a2; g_Cc[d] = c;
}

// ---------------------------------------------------------------------------
__global__ void __launch_bounds__(256) softmax_kernel(float* __restrict__ attn)
{
    __shared__ float red[256];
    const size_t base = (size_t)blockIdx.x * VL;
    const int t = threadIdx.x;
    float x[8];
    float mx = -1e30f;
#pragma unroll
    for (int i = 0; i < 8; i++) { x[i] = attn[base + t + 256 * i]; mx = fmaxf(mx, x[i]); }
    red[t] = mx; __syncthreads();
    for (int s = 128; s > 0; s >>= 1) { if (t < s) red[t] = fmaxf(red[t], red[t + s]); __syncthreads(); }
    mx = red[0];
    __syncthreads();
    float sum = 0.f;
#pragma unroll
    for (int i = 0; i < 8; i++) { x[i] = __expf(x[i] - mx); sum += x[i]; }
    red[t] = sum; __syncthreads();
    for (int s = 128; s > 0; s >>= 1) { if (t < s) red[t] += red[t + s]; __syncthreads(); }
    float inv = 1.0f / red[0];
#pragma unroll
    for (int i = 0; i < 8; i++) attn[base + t + 256 * i] = x[i] * inv;
}

// ---------------------------------------------------------------------------
extern "C" void kernel_launch(void* const* d_in, const int* in_sizes, int n_in,
                              void* d_out, int out_size)
{
    const float* q         = (const float*)d_in[0];
    const float* v         = (const float*)d_in[1];
    const float* last_attn = (const float*)d_in[2];
    const float* conv_w    = (const float*)d_in[3];
    const float* conv_b    = (const float*)d_in[4];
    const float* Wq        = (const float*)d_in[5];
    const float* bq        = (const float*)d_in[6];
    const float* Wv        = (const float*)d_in[7];
    const float* Wloc      = (const float*)d_in[8];
    const float* bias      = (const float*)d_in[9];

    float* out  = (float*)d_out;
    float* attn = out + 4194304;

    prep_kernel<<<1, 128>>>(conv_w, conv_b, Wloc);
    mma_gemm<0><<<dim3(8, 32),   256, SMEM_SZ>>>(q, Wq, bq, nullptr, nullptr);
    mma_gemm<1><<<dim3(8, 512),  256, SMEM_SZ>>>(v, Wv, bias, last_attn, nullptr);
    mma_gemm<2><<<dim3(16, 256), 256, SMEM_SZ>>>(nullptr, nullptr, nullptr, nullptr, attn);
    softmax_kernel<<<32768, 256>>>(attn);
    mma_gemm<3><<<256, 256, SMEM_SZ>>>(attn, nullptr, nullptr, nullptr, out);
}

// round 4
// speedup vs baseline: 2.4939x; 1.4217x over previous
#include <cuda_runtime.h>
#include <cuda_fp16.h>
#include <cstdint>

#define DI __device__ __forceinline__

static const int QL  = 128;
static const int VL  = 2048;
static const int HID = 1024;

// ---------------------------------------------------------------------------
// Scratch (device globals; no runtime allocation allowed). fp16 operands.
// ---------------------------------------------------------------------------
__device__ uint16_t s_q_h[4194304],  s_q_l[4194304];    // split q
__device__ uint16_t s_v_h[67108864], s_v_l[67108864];   // split v
__device__ uint16_t s_Wq_h[1048576];                    // Wq hi (B-side only)
__device__ uint16_t s_Wv_h[1048576];                    // Wv hi
__device__ uint16_t g_qh_h[4194304], g_qh_l[4194304];   // qp result [n][q][d]
__device__ uint16_t g_vh_h[67108864];                   // vp result [n][v][d]
__device__ uint16_t g_vhT_h[67108864];                  // vp result [n][d][v]
__device__ float g_A0[128], g_A1[128], g_A2[128], g_Cc[128];

// ---------------------------------------------------------------------------
DI uint32_t smem_u32(const void* p) {
    uint32_t a;
    asm("{ .reg .u64 t; cvta.to.shared.u64 t, %1; cvt.u32.u64 %0, t; }" : "=r"(a) : "l"(p));
    return a;
}

// split (a,b) -> fp16x2 hi (returned, a in low half) and fp16x2 lo (out)
DI uint32_t sp2h(float a, float b, uint32_t& lo) {
    __half2 h = __floats2half2_rn(a, b);
    float2 f = __half22float2(h);
    __half2 l = __floats2half2_rn(a - f.x, b - f.y);
    lo = *(uint32_t*)&l;
    return *(uint32_t*)&h;
}
DI uint32_t pk2h(float a, float b) {
    __half2 h = __floats2half2_rn(a, b);
    return *(uint32_t*)&h;
}

DI void ldm4(uint32_t* r, uint32_t a) {
    asm volatile("ldmatrix.sync.aligned.m8n8.x4.shared.b16 {%0,%1,%2,%3}, [%4];"
        : "=r"(r[0]), "=r"(r[1]), "=r"(r[2]), "=r"(r[3]) : "r"(a));
}

DI void mma16816(float* d, const uint32_t* a, uint32_t b0, uint32_t b1) {
    asm volatile("mma.sync.aligned.m16n8k16.row.col.f32.f16.f16.f32 "
        "{%0,%1,%2,%3},{%4,%5,%6,%7},{%8,%9},{%0,%1,%2,%3};"
        : "+f"(d[0]), "+f"(d[1]), "+f"(d[2]), "+f"(d[3])
        : "r"(a[0]), "r"(a[1]), "r"(a[2]), "r"(a[3]), "r"(b0), "r"(b1));
}

DI void cp16(uint32_t dst, const void* src) {
    asm volatile("cp.async.cg.shared.global [%0], [%1], 16;" :: "r"(dst), "l"(src));
}
#define CP_COMMIT() asm volatile("cp.async.commit_group;" ::: "memory")
#define CP_WAIT1()  asm volatile("cp.async.wait_group 1;"  ::: "memory")

// ---------------------------------------------------------------------------
// smem: 2 buffers x 3 tiles (Ah, Al, Bh) of [128 rows x 80B]. 61440 bytes.
// Row r, k-slot s (8 fp16) at r*80 + s*16 -> conflict-free ldmatrix.
// ---------------------------------------------------------------------------
static const int TILE_B  = 10240;
static const int BUFSZ   = 3 * TILE_B;   // 30720
static const int SMEM_SZ = 2 * BUFSZ;    // 61440

// cp.async one K-chunk (A hi/lo + B hi), 1536 16B-copies / 256 threads
DI void cp_chunk(char* smbuf, const uint16_t* Ah, const uint16_t* Al,
                 const uint16_t* Bh, int lda, int ldb, int c) {
    const int t = threadIdx.x;
    uint32_t sb = smem_u32(smbuf);
#pragma unroll
    for (int i = 0; i < 6; i++) {
        int idx = t + 256 * i;
        int tile = idx >> 9, r = (idx >> 2) & 127, s = idx & 3;
        const uint16_t* base = (tile == 0) ? Ah : (tile == 1) ? Al : Bh;
        int ld = (tile == 2) ? ldb : lda;
        cp16(sb + tile * TILE_B + r * 80 + s * 16,
             base + (size_t)r * ld + c * 32 + s * 8);
    }
}
// B-only variant (MODE 3)
DI void cp_chunk_b(char* smbuf, const uint16_t* Bh, int ldb, int c) {
    const int t = threadIdx.x;
    uint32_t sb = smem_u32(smbuf);
#pragma unroll
    for (int i = 0; i < 2; i++) {
        int idx = t + 256 * i;
        int r = (idx >> 2) & 127, s = idx & 3;
        cp16(sb + 2 * TILE_B + r * 80 + s * 16,
             Bh + (size_t)r * ldb + c * 32 + s * 8);
    }
}

// 2-pass mma on one chunk: aH*bH + aL*bH
DI void compute_chunk(uint32_t sbuf, int lane, int wm0, int wn0, float acc[2][8][4]) {
#pragma unroll
    for (int ks = 0; ks < 2; ks++) {
        const uint32_t rowsel = (uint32_t)(lane & 15) * 80
                              + (uint32_t)((lane >> 4) + ks * 2) * 16;
        uint32_t aH[2][4], aL[2][4], bH[4][4];
#pragma unroll
        for (int mt = 0; mt < 2; mt++) {
            uint32_t ad = sbuf + (uint32_t)(wm0 + mt * 16) * 80 + rowsel;
            ldm4(aH[mt], ad);
            ldm4(aL[mt], ad + TILE_B);
        }
#pragma unroll
        for (int g = 0; g < 4; g++)
            ldm4(bH[g], sbuf + 2 * TILE_B + (uint32_t)(wn0 + g * 16) * 80 + rowsel);
#pragma unroll
        for (int mt = 0; mt < 2; mt++)
#pragma unroll
            for (int g = 0; g < 4; g++) {
                mma16816(acc[mt][2 * g],     aH[mt], bH[g][0], bH[g][2]);
                mma16816(acc[mt][2 * g + 1], aH[mt], bH[g][1], bH[g][3]);
            }
#pragma unroll
        for (int mt = 0; mt < 2; mt++)
#pragma unroll
            for (int g = 0; g < 4; g++) {
                mma16816(acc[mt][2 * g],     aL[mt], bH[g][0], bH[g][2]);
                mma16816(acc[mt][2 * g + 1], aL[mt], bH[g][1], bH[g][3]);
            }
    }
}

// ---------------------------------------------------------------------------
// MODE 0: qp = q@Wq^T + bq          -> g_qh_h/l        grid(8, 32)
// MODE 1: vp = v@Wv^T + bias + loc  -> g_vh_h, g_vhT_h grid(8, 512)
// MODE 2: score = qh@vh^T * sc      -> attn (fp32)     grid(16, 256)
// MODE 3: out = attn@vh             -> out  (fp32)     grid(256)
// ---------------------------------------------------------------------------
template <int MODE>
__global__ void __launch_bounds__(256)
mma_gemm(const float* __restrict__ attn_in, const float* __restrict__ biasv,
         const float* __restrict__ la, float* __restrict__ dsto)
{
    extern __shared__ char sm[];
    const uint32_t smb = smem_u32(sm);
    const int t = threadIdx.x, lane = t & 31, w = t >> 5;
    const int wm0 = (w & 3) * 32, wn0 = (w >> 2) * 64;

    constexpr int K  = (MODE < 2) ? HID : (MODE == 2 ? 128 : VL);
    constexpr int NC = K / 32;

    const uint16_t *Ah = nullptr, *Al = nullptr, *Bh = nullptr;
    const float* Afp = nullptr;
    int lda = 0, ldb = 0;
    if (MODE == 0) {
        size_t ao = (size_t)blockIdx.y * 128 * HID, bo = (size_t)blockIdx.x * 128 * HID;
        Ah = s_q_h + ao; Al = s_q_l + ao; Bh = s_Wq_h + bo; lda = ldb = HID;
    } else if (MODE == 1) {
        size_t ao = (size_t)blockIdx.y * 128 * HID, bo = (size_t)blockIdx.x * 128 * HID;
        Ah = s_v_h + ao; Al = s_v_l + ao; Bh = s_Wv_h + bo; lda = ldb = HID;
    } else if (MODE == 2) {
        size_t ao = (size_t)blockIdx.y * QL * 128;
        size_t bo = (size_t)blockIdx.y * VL * 128 + (size_t)blockIdx.x * 128 * 128;
        Ah = g_qh_h + ao; Al = g_qh_l + ao; Bh = g_vh_h + bo; lda = ldb = 128;
    } else {
        Afp = attn_in + (size_t)blockIdx.x * QL * VL;
        Bh  = g_vhT_h + (size_t)blockIdx.x * 128 * VL; ldb = VL;
    }

    float acc[2][8][4];
#pragma unroll
    for (int i = 0; i < 2; i++)
#pragma unroll
        for (int j = 0; j < 8; j++)
#pragma unroll
            for (int k = 0; k < 4; k++) acc[i][j][k] = 0.f;

    // MODE 3 A-operand register path (fp32 attn -> fp16 split in-kernel)
    float4 arg[4];
    const float* ap3 = (MODE == 3) ? Afp + (size_t)(t >> 1) * VL + (t & 1) * 16 : nullptr;
    const uint32_t aoff3 = (t >> 1) * 80 + (t & 1) * 32;

#define LD_A3(c)  { _Pragma("unroll") for (int j = 0; j < 4; j++) arg[j] = *(const float4*)(ap3 + (c) * 32 + j * 4); }
#define STS_A3(buf) { \
        char* bb = sm + (buf) * BUFSZ;                                        \
        uint4 H, L;                                                           \
        H.x = sp2h(arg[0].x, arg[0].y, L.x); H.y = sp2h(arg[0].z, arg[0].w, L.y); \
        H.z = sp2h(arg[1].x, arg[1].y, L.z); H.w = sp2h(arg[1].z, arg[1].w, L.w); \
        *(uint4*)(bb + aoff3) = H; *(uint4*)(bb + TILE_B + aoff3) = L;        \
        H.x = sp2h(arg[2].x, arg[2].y, L.x); H.y = sp2h(arg[2].z, arg[2].w, L.y); \
        H.z = sp2h(arg[3].x, arg[3].y, L.z); H.w = sp2h(arg[3].z, arg[3].w, L.w); \
        *(uint4*)(bb + aoff3 + 16) = H; *(uint4*)(bb + TILE_B + aoff3 + 16) = L; }

    // prologue: prefill both buffers
    if (MODE == 3) {
        LD_A3(0); STS_A3(0);
        LD_A3(1); STS_A3(1);
        LD_A3(2);
        cp_chunk_b(sm, Bh, ldb, 0);         CP_COMMIT();
        cp_chunk_b(sm + BUFSZ, Bh, ldb, 1); CP_COMMIT();
    } else {
        cp_chunk(sm, Ah, Al, Bh, lda, ldb, 0);         CP_COMMIT();
        cp_chunk(sm + BUFSZ, Ah, Al, Bh, lda, ldb, 1); CP_COMMIT();
    }

    for (int c = 0; c < NC; c++) {
        CP_WAIT1();
        __syncthreads();
        compute_chunk(smb + (c & 1) * BUFSZ, lane, wm0, wn0, acc);
        __syncthreads();
        if (c + 2 < NC) {
            if (MODE == 3) {
                STS_A3(c & 1);
                cp_chunk_b(sm + (c & 1) * BUFSZ, Bh, ldb, c + 2);
                if (c + 3 < NC) LD_A3(c + 3);
            } else {
                cp_chunk(sm + (c & 1) * BUFSZ, Ah, Al, Bh, lda, ldb, c + 2);
            }
        }
        CP_COMMIT();
    }

    // ------------------------- epilogue -------------------------
    float* vec = (float*)(sm + 34048);
    if (MODE == 0) {
        if (t < 128) vec[t] = biasv[blockIdx.x * 128 + t];
    }
    if (MODE == 1) {
        if (t < 128) {
            vec[t]       = biasv[blockIdx.x * 128 + t] + g_Cc[t];
            vec[128 + t] = g_A0[t];
            vec[256 + t] = g_A1[t];
            vec[384 + t] = g_A2[t];
        }
        const int b = blockIdx.y >> 4, h = blockIdx.x;
        const int vpos0 = (blockIdx.y & 15) * 128;
        const float* lar = la + (size_t)(b * 8 + h) * VL;
        if (t < 130) {
            int g = vpos0 - 1 + t;
            vec[512 + t] = (g >= 0 && g < VL) ? lar[g] : 0.f;
        }
    }
    __syncthreads();

#pragma unroll
    for (int mt = 0; mt < 2; mt++) {
#pragma unroll
        for (int h2 = 0; h2 < 2; h2++) {
            const int row = wm0 + mt * 16 + (lane >> 2) + h2 * 8;
            size_t obase = 0;
            float* dst = nullptr;
            float lm1 = 0.f, l0 = 0.f, lp1 = 0.f;
            if (MODE == 0) {
                obase = (((size_t)(blockIdx.x * 32 + blockIdx.y)) * QL + row) * 128;
            } else if (MODE == 1) {
                int b = blockIdx.y >> 4, h = blockIdx.x;
                int vpos0 = (blockIdx.y & 15) * 128;
                lm1 = vec[512 + row]; l0 = vec[513 + row]; lp1 = vec[514 + row];
                obase = (((size_t)(h * 32 + b)) * VL + vpos0 + row) * 128;
            } else if (MODE == 2) {
                dst = dsto + ((size_t)blockIdx.y * QL + row) * VL + blockIdx.x * 128;
            } else {
                int h = blockIdx.x >> 5, b = blockIdx.x & 31;
                dst = dsto + ((size_t)(b * QL + row)) * HID + h * 128;
            }
#pragma unroll
            for (int nt = 0; nt < 8; nt++) {
                const int col = wn0 + nt * 8 + 2 * (lane & 3);
                float x = acc[mt][nt][2 * h2];
                float y = acc[mt][nt][2 * h2 + 1];
                if (MODE == 0) {
                    x += vec[col]; y += vec[col + 1];
                    uint32_t lo, hi = sp2h(x, y, lo);
                    *(uint32_t*)&g_qh_h[obase + col] = hi;
                    *(uint32_t*)&g_qh_l[obase + col] = lo;
                } else if (MODE == 1) {
                    x += vec[col]     + vec[128 + col]     * lm1 + vec[256 + col]     * l0 + vec[384 + col]     * lp1;
                    y += vec[col + 1] + vec[128 + col + 1] * lm1 + vec[256 + col + 1] * l0 + vec[384 + col + 1] * lp1;
                    uint32_t hi = pk2h(x, y);
                    *(uint32_t*)&g_vh_h[obase + col] = hi;
                    // stage transposed copy: [v=row][d=col] pitch 65 words
                    *(uint32_t*)(sm + (row * 65 + (col >> 1)) * 4) = hi;
                } else if (MODE == 2) {
                    const float sc = 0.08838834764831845f;
                    *(float2*)(dst + col) = make_float2(x * sc, y * sc);
                } else {
                    *(float2*)(dst + col) = make_float2(x, y);
                }
            }
        }
    }

    if (MODE == 1) {
        __syncthreads();
        // write g_vhT: thread t -> d = t>>1, v-half = t&1 (64 v each)
        const int b = blockIdx.y >> 4, h = blockIdx.x;
        const int vpos0 = (blockIdx.y & 15) * 128;
        const int d = t >> 1, vh2 = t & 1;
        size_t ob = (((size_t)(h * 32 + b)) * 128 + d) * VL + vpos0 + vh2 * 64;
#pragma unroll
        for (int blk = 0; blk < 8; blk++) {
            uint16_t e[8];
#pragma unroll
            for (int j = 0; j < 8; j++) {
                int v = vh2 * 64 + blk * 8 + j;
                e[j] = *(uint16_t*)(sm + (v * 65 + (d >> 1)) * 4 + (d & 1) * 2);
            }
            uint4 o;
            o.x = (uint32_t)e[0] | ((uint32_t)e[1] << 16);
            o.y = (uint32_t)e[2] | ((uint32_t)e[3] << 16);
            o.z = (uint32_t)e[4] | ((uint32_t)e[5] << 16);
            o.w = (uint32_t)e[6] | ((uint32_t)e[7] << 16);
            *(uint4*)&g_vhT_h[ob + blk * 8] = o;
        }
    }
}

// ---------------------------------------------------------------------------
// elementwise fp32 -> fp16 hi/lo split
// ---------------------------------------------------------------------------
DI void split_body(const float4* __restrict__ in, uint16_t* oh, uint16_t* ol, int n4) {
    int i = blockIdx.x * 256 + threadIdx.x;
    if (i >= n4) return;
    float4 x = in[i];
    uint32_t l0, l1;
    uint32_t h0 = sp2h(x.x, x.y, l0), h1 = sp2h(x.z, x.w, l1);
    uint2 H; H.x = h0; H.y = h1;
    *(uint2*)&oh[(size_t)i * 4] = H;
    if (ol) { uint2 L; L.x = l0; L.y = l1; *(uint2*)&ol[(size_t)i * 4] = L; }
}
__global__ void split_q_k(const float4* in)  { split_body(in, s_q_h, s_q_l, 1048576); }
__global__ void split_v_k(const float4* in)  { split_body(in, s_v_h, s_v_l, 16777216); }
__global__ void split_wq_k(const float4* in) { split_body(in, s_Wq_h, nullptr, 262144); }
__global__ void split_wv_k(const float4* in) { split_body(in, s_Wv_h, nullptr, 262144); }

// ---------------------------------------------------------------------------
__global__ void prep_kernel(const float* __restrict__ conv_w,
                            const float* __restrict__ conv_b,
                            const float* __restrict__ Wloc)
{
    int d = threadIdx.x;
    float a0 = 0.f, a1 = 0.f, a2 = 0.f, c = 0.f;
#pragma unroll
    for (int cc = 0; cc < 10; cc++) {
        float wl = Wloc[d * 10 + cc];
        a0 += wl * conv_w[cc * 3 + 0];
        a1 += wl * conv_w[cc * 3 + 1];
        a2 += wl * conv_w[cc * 3 + 2];
        c  += wl * conv_b[cc];
    }
    g_A0[d] = a0; g_A1[d] = a1; g_A2[d] = a2; g_Cc[d] = c;
}

// ---------------------------------------------------------------------------
__global__ void __launch_bounds__(256) softmax_kernel(float* __restrict__ attn)
{
    __shared__ float sm1[8], sm2[8];
    const size_t base = (size_t)blockIdx.x * VL;
    const int t = threadIdx.x, lane = t & 31, w = t >> 5;
    float4 a = *(float4*)(attn + base + t * 4);
    float4 b = *(float4*)(attn + base + 1024 + t * 4);
    float m = fmaxf(fmaxf(fmaxf(a.x, a.y), fmaxf(a.z, a.w)),
                    fmaxf(fmaxf(b.x, b.y), fmaxf(b.z, b.w)));
#pragma unroll
    for (int s = 16; s; s >>= 1) m = fmaxf(m, __shfl_xor_sync(~0u, m, s));
    if (lane == 0) sm1[w] = m;
    __syncthreads();
    m = sm1[0];
#pragma unroll
    for (int i = 1; i < 8; i++) m = fmaxf(m, sm1[i]);
    a.x = __expf(a.x - m); a.y = __expf(a.y - m); a.z = __expf(a.z - m); a.w = __expf(a.w - m);
    b.x = __expf(b.x - m); b.y = __expf(b.y - m); b.z = __expf(b.z - m); b.w = __expf(b.w - m);
    float s = a.x + a.y + a.z + a.w + b.x + b.y + b.z + b.w;
#pragma unroll
    for (int sh = 16; sh; sh >>= 1) s += __shfl_xor_sync(~0u, s, sh);
    if (lane == 0) sm2[w] = s;
    __syncthreads();
    s = sm2[0];
#pragma unroll
    for (int i = 1; i < 8; i++) s += sm2[i];
    float inv = 1.0f / s;
    a.x *= inv; a.y *= inv; a.z *= inv; a.w *= inv;
    b.x *= inv; b.y *= inv; b.z *= inv; b.w *= inv;
    *(float4*)(attn + base + t * 4) = a;
    *(float4*)(attn + base + 1024 + t * 4) = b;
}

// ---------------------------------------------------------------------------
extern "C" void kernel_launch(void* const* d_in, const int* in_sizes, int n_in,
                              void* d_out, int out_size)
{
    const float* q         = (const float*)d_in[0];
    const float* v         = (const float*)d_in[1];
    const float* last_attn = (const float*)d_in[2];
    const float* conv_w    = (const float*)d_in[3];
    const float* conv_b    = (const float*)d_in[4];
    const float* Wq        = (const float*)d_in[5];
    const float* bq        = (const float*)d_in[6];
    const float* Wv        = (const float*)d_in[7];
    const float* Wloc      = (const float*)d_in[8];
    const float* bias      = (const float*)d_in[9];

    float* out  = (float*)d_out;
    float* attn = out + 4194304;

    static bool attr_done = false;
    if (!attr_done) {
        cudaFuncSetAttribute(mma_gemm<0>, cudaFuncAttributeMaxDynamicSharedMemorySize, SMEM_SZ);
        cudaFuncSetAttribute(mma_gemm<1>, cudaFuncAttributeMaxDynamicSharedMemorySize, SMEM_SZ);
        cudaFuncSetAttribute(mma_gemm<2>, cudaFuncAttributeMaxDynamicSharedMemorySize, SMEM_SZ);
        cudaFuncSetAttribute(mma_gemm<3>, cudaFuncAttributeMaxDynamicSharedMemorySize, SMEM_SZ);
        attr_done = true;
    }

    prep_kernel<<<1, 128>>>(conv_w, conv_b, Wloc);
    split_q_k <<<4096,  256>>>((const float4*)q);
    split_v_k <<<65536, 256>>>((const float4*)v);
    split_wq_k<<<1024,  256>>>((const float4*)Wq);
    split_wv_k<<<1024,  256>>>((const float4*)Wv);

    mma_gemm<0><<<dim3(8, 32),   256, SMEM_SZ>>>(nullptr, bq,   nullptr,   nullptr);
    mma_gemm<1><<<dim3(8, 512),  256, SMEM_SZ>>>(nullptr, bias, last_attn, nullptr);
    mma_gemm<2><<<dim3(16, 256), 256, SMEM_SZ>>>(nullptr, nullptr, nullptr, attn);
    softmax_kernel<<<32768, 256>>>(attn);
    mma_gemm<3><<<256, 256, SMEM_SZ>>>(attn, nullptr, nullptr, out);
}

// round 5
// speedup vs baseline: 3.3562x; 1.3457x over previous
#include <cuda_runtime.h>
#include <cuda_fp16.h>
#include <cstdint>

#define DI __device__ __forceinline__

static const int QL  = 128;
static const int VL  = 2048;
static const int HID = 1024;

// ---------------------------------------------------------------------------
// Scratch (device globals; no runtime allocation allowed). fp16 operands.
// ---------------------------------------------------------------------------
__device__ uint16_t s_q_h[4194304],  s_q_l[4194304];    // split q
__device__ uint16_t s_v_h[67108864];                    // v hi only (1-pass A)
__device__ uint16_t s_Wq_h[1048576];                    // Wq hi (B-side only)
__device__ uint16_t s_Wv_h[1048576];                    // Wv hi
__device__ uint16_t g_qh_h[4194304], g_qh_l[4194304];   // qp result [n][q][d]
__device__ uint16_t g_vh_h[67108864];                   // vp result [n][v][d]
__device__ uint16_t g_vhT_h[67108864];                  // vp result [n][d][v]
__device__ float g_A0[128], g_A1[128], g_A2[128], g_Cc[128];

// ---------------------------------------------------------------------------
DI uint32_t smem_u32(const void* p) {
    uint32_t a;
    asm("{ .reg .u64 t; cvta.to.shared.u64 t, %1; cvt.u32.u64 %0, t; }" : "=r"(a) : "l"(p));
    return a;
}

// split (a,b) -> fp16x2 hi (returned, a in low half) and fp16x2 lo (out)
DI uint32_t sp2h(float a, float b, uint32_t& lo) {
    __half2 h = __floats2half2_rn(a, b);
    float2 f = __half22float2(h);
    __half2 l = __floats2half2_rn(a - f.x, b - f.y);
    lo = *(uint32_t*)&l;
    return *(uint32_t*)&h;
}
DI uint32_t pk2h(float a, float b) {
    __half2 h = __floats2half2_rn(a, b);
    return *(uint32_t*)&h;
}

DI void ldm4(uint32_t* r, uint32_t a) {
    asm volatile("ldmatrix.sync.aligned.m8n8.x4.shared.b16 {%0,%1,%2,%3}, [%4];"
        : "=r"(r[0]), "=r"(r[1]), "=r"(r[2]), "=r"(r[3]) : "r"(a));
}

DI void mma16816(float* d, const uint32_t* a, uint32_t b0, uint32_t b1) {
    asm volatile("mma.sync.aligned.m16n8k16.row.col.f32.f16.f16.f32 "
        "{%0,%1,%2,%3},{%4,%5,%6,%7},{%8,%9},{%0,%1,%2,%3};"
        : "+f"(d[0]), "+f"(d[1]), "+f"(d[2]), "+f"(d[3])
        : "r"(a[0]), "r"(a[1]), "r"(a[2]), "r"(a[3]), "r"(b0), "r"(b1));
}

DI void cp16(uint32_t dst, const void* src) {
    asm volatile("cp.async.cg.shared.global [%0], [%1], 16;" :: "r"(dst), "l"(src));
}
#define CP_COMMIT() asm volatile("cp.async.commit_group;" ::: "memory")
#define CP_WAIT2()  asm volatile("cp.async.wait_group 2;"  ::: "memory")

// ---------------------------------------------------------------------------
// Tiles: [128 rows x 80B] (32 fp16 + 16B pad) -> conflict-free ldmatrix.
// 3-stage pipeline; NT tiles per stage (mode1: Ah,Bh; others: Ah,Al,Bh).
// ---------------------------------------------------------------------------
static const int TILE_B = 10240;

// MODE 0: qp = q@Wq^T + bq          -> g_qh_h/l        grid(8, 32)
// MODE 1: vp = v@Wv^T + bias + loc  -> g_vh_h, g_vhT_h grid(8, 512)  (A 1-pass)
// MODE 2: score = qh@vh^T * sc      -> attn (fp32)     grid(16, 256)
// MODE 3: out = attn@vh             -> out  (fp32)     grid(256)
template <int MODE>
__global__ void __launch_bounds__(256)
mma_gemm(const float* __restrict__ attn_in, const float* __restrict__ biasv,
         const float* __restrict__ la, float* __restrict__ dsto)
{
    extern __shared__ char sm[];
    const uint32_t smb = smem_u32(sm);
    const int t = threadIdx.x, lane = t & 31, w = t >> 5;
    const int wm0 = (w & 3) * 32, wn0 = (w >> 2) * 64;

    constexpr int K   = (MODE < 2) ? HID : (MODE == 2 ? 128 : VL);
    constexpr int NC  = K / 32;
    constexpr int NPA = (MODE == 1) ? 1 : 2;
    constexpr int NT  = (MODE == 1) ? 2 : 3;
    constexpr int BUF = NT * TILE_B;
    constexpr uint32_t BOFF = (uint32_t)(NT - 1) * TILE_B;

    const uint16_t *Ah = nullptr, *Al = nullptr, *Bh = nullptr;
    const float* Afp = nullptr;
    int lda = 0, ldb = 0;
    if (MODE == 0) {
        size_t ao = (size_t)blockIdx.y * 128 * HID, bo = (size_t)blockIdx.x * 128 * HID;
        Ah = s_q_h + ao; Al = s_q_l + ao; Bh = s_Wq_h + bo; lda = ldb = HID;
    } else if (MODE == 1) {
        size_t ao = (size_t)blockIdx.y * 128 * HID, bo = (size_t)blockIdx.x * 128 * HID;
        Ah = s_v_h + ao; Bh = s_Wv_h + bo; lda = ldb = HID;
    } else if (MODE == 2) {
        size_t ao = (size_t)blockIdx.y * QL * 128;
        size_t bo = (size_t)blockIdx.y * VL * 128 + (size_t)blockIdx.x * 128 * 128;
        Ah = g_qh_h + ao; Al = g_qh_l + ao; Bh = g_vh_h + bo; lda = ldb = 128;
    } else {
        Afp = attn_in + (size_t)blockIdx.x * QL * VL;
        Bh  = g_vhT_h + (size_t)blockIdx.x * 128 * VL; ldb = VL;
    }

    float acc[2][8][4];
#pragma unroll
    for (int i = 0; i < 2; i++)
#pragma unroll
        for (int j = 0; j < 8; j++)
#pragma unroll
            for (int k = 0; k < 4; k++) acc[i][j][k] = 0.f;

    // ---- cp.async one chunk (modes 0/1/2: all tiles) ----
    auto cp_chunk = [&](int buf, int c) {
        uint32_t sb = smb + buf * BUF;
#pragma unroll
        for (int i = 0; i < NT * 2; i++) {
            int idx = t + 256 * i;
            int tile = idx >> 9, r = (idx >> 2) & 127, s = idx & 3;
            const uint16_t* base; int ld; uint32_t doff;
            if (NT == 2) {
                base = tile ? Bh : Ah; ld = tile ? ldb : lda;
                doff = tile ? TILE_B : 0u;
            } else {
                base = (tile == 0) ? Ah : (tile == 1) ? Al : Bh;
                ld = (tile == 2) ? ldb : lda;
                doff = (uint32_t)tile * TILE_B;
            }
            cp16(sb + doff + r * 80 + s * 16, base + (size_t)r * ld + c * 32 + s * 8);
        }
    };
    // ---- MODE 3: B only ----
    auto cp_chunk_b = [&](int buf, int c) {
        uint32_t sb = smb + buf * BUF + 2 * TILE_B;
#pragma unroll
        for (int i = 0; i < 2; i++) {
            int idx = t + 256 * i;
            int r = (idx >> 2) & 127, s = idx & 3;
            cp16(sb + r * 80 + s * 16, Bh + (size_t)r * ldb + c * 32 + s * 8);
        }
    };

    auto compute = [&](uint32_t sbuf) {
#pragma unroll
        for (int ks = 0; ks < 2; ks++) {
            const uint32_t rowsel = (uint32_t)(lane & 15) * 80
                                  + (uint32_t)((lane >> 4) + ks * 2) * 16;
            uint32_t aH[2][4], aL[2][4], bH[4][4];
#pragma unroll
            for (int mt = 0; mt < 2; mt++) {
                uint32_t ad = sbuf + (uint32_t)(wm0 + mt * 16) * 80 + rowsel;
                ldm4(aH[mt], ad);
                if (NPA == 2) ldm4(aL[mt], ad + TILE_B);
            }
#pragma unroll
            for (int g = 0; g < 4; g++)
                ldm4(bH[g], sbuf + BOFF + (uint32_t)(wn0 + g * 16) * 80 + rowsel);
#pragma unroll
            for (int mt = 0; mt < 2; mt++)
#pragma unroll
                for (int g = 0; g < 4; g++) {
                    mma16816(acc[mt][2 * g],     aH[mt], bH[g][0], bH[g][2]);
                    mma16816(acc[mt][2 * g + 1], aH[mt], bH[g][1], bH[g][3]);
                }
            if (NPA == 2) {
#pragma unroll
                for (int mt = 0; mt < 2; mt++)
#pragma unroll
                    for (int g = 0; g < 4; g++) {
                        mma16816(acc[mt][2 * g],     aL[mt], bH[g][0], bH[g][2]);
                        mma16816(acc[mt][2 * g + 1], aL[mt], bH[g][1], bH[g][3]);
                    }
            }
        }
    };

    // MODE 3 A-operand register path (fp32 attn -> fp16 split in-kernel)
    float4 arg[4];
    const float* ap3 = (MODE == 3) ? Afp + (size_t)(t >> 1) * VL + (t & 1) * 16 : nullptr;
    const uint32_t aoff3 = (t >> 1) * 80 + (t & 1) * 32;

#define LD_A3(c)  { _Pragma("unroll") for (int j = 0; j < 4; j++) arg[j] = *(const float4*)(ap3 + (c) * 32 + j * 4); }
#define STS_A3(buf) { \
        char* bb = sm + (buf) * BUF;                                          \
        uint4 H, L;                                                           \
        H.x = sp2h(arg[0].x, arg[0].y, L.x); H.y = sp2h(arg[0].z, arg[0].w, L.y); \
        H.z = sp2h(arg[1].x, arg[1].y, L.z); H.w = sp2h(arg[1].z, arg[1].w, L.w); \
        *(uint4*)(bb + aoff3) = H; *(uint4*)(bb + TILE_B + aoff3) = L;        \
        H.x = sp2h(arg[2].x, arg[2].y, L.x); H.y = sp2h(arg[2].z, arg[2].w, L.y); \
        H.z = sp2h(arg[3].x, arg[3].y, L.z); H.w = sp2h(arg[3].z, arg[3].w, L.w); \
        *(uint4*)(bb + aoff3 + 16) = H; *(uint4*)(bb + TILE_B + aoff3 + 16) = L; }

    // ---- prologue: fill 3 stages ----
    if (MODE == 3) {
        LD_A3(0); STS_A3(0);
        LD_A3(1); STS_A3(1);
        LD_A3(2); STS_A3(2);
        LD_A3(3);
        cp_chunk_b(0, 0); CP_COMMIT();
        cp_chunk_b(1, 1); CP_COMMIT();
        cp_chunk_b(2, 2); CP_COMMIT();
    } else {
        cp_chunk(0, 0); CP_COMMIT();
        cp_chunk(1, 1); CP_COMMIT();
        cp_chunk(2, 2); CP_COMMIT();
    }

    int buf = 0;
    for (int c = 0; c < NC; c++) {
        CP_WAIT2();
        __syncthreads();
        compute(smb + buf * BUF);
        __syncthreads();
        if (c + 3 < NC) {
            if (MODE == 3) {
                STS_A3(buf);
                cp_chunk_b(buf, c + 3);
            } else {
                cp_chunk(buf, c + 3);
            }
        }
        CP_COMMIT();
        if (MODE == 3 && c + 4 < NC) LD_A3(c + 4);
        buf = (buf == 2) ? 0 : buf + 1;
    }

    // ------------------------- epilogue -------------------------
    float* vec = (float*)(sm + 34048);
    if (MODE == 0) {
        if (t < 128) vec[t] = biasv[blockIdx.x * 128 + t];
    }
    if (MODE == 1) {
        if (t < 128) {
            vec[t]       = biasv[blockIdx.x * 128 + t] + g_Cc[t];
            vec[128 + t] = g_A0[t];
            vec[256 + t] = g_A1[t];
            vec[384 + t] = g_A2[t];
        }
        const int b = blockIdx.y >> 4, h = blockIdx.x;
        const int vpos0 = (blockIdx.y & 15) * 128;
        const float* lar = la + (size_t)(b * 8 + h) * VL;
        if (t < 130) {
            int g = vpos0 - 1 + t;
            vec[512 + t] = (g >= 0 && g < VL) ? lar[g] : 0.f;
        }
    }
    __syncthreads();

#pragma unroll
    for (int mt = 0; mt < 2; mt++) {
#pragma unroll
        for (int h2 = 0; h2 < 2; h2++) {
            const int row = wm0 + mt * 16 + (lane >> 2) + h2 * 8;
            size_t obase = 0;
            float* dst = nullptr;
            float lm1 = 0.f, l0 = 0.f, lp1 = 0.f;
            if (MODE == 0) {
                obase = (((size_t)(blockIdx.x * 32 + blockIdx.y)) * QL + row) * 128;
            } else if (MODE == 1) {
                int b = blockIdx.y >> 4, h = blockIdx.x;
                int vpos0 = (blockIdx.y & 15) * 128;
                lm1 = vec[512 + row]; l0 = vec[513 + row]; lp1 = vec[514 + row];
                obase = (((size_t)(h * 32 + b)) * VL + vpos0 + row) * 128;
            } else if (MODE == 2) {
                dst = dsto + ((size_t)blockIdx.y * QL + row) * VL + blockIdx.x * 128;
            } else {
                int h = blockIdx.x >> 5, b = blockIdx.x & 31;
                dst = dsto + ((size_t)(b * QL + row)) * HID + h * 128;
            }
#pragma unroll
            for (int nt = 0; nt < 8; nt++) {
                const int col = wn0 + nt * 8 + 2 * (lane & 3);
                float x = acc[mt][nt][2 * h2];
                float y = acc[mt][nt][2 * h2 + 1];
                if (MODE == 0) {
                    x += vec[col]; y += vec[col + 1];
                    uint32_t lo, hi = sp2h(x, y, lo);
                    *(uint32_t*)&g_qh_h[obase + col] = hi;
                    *(uint32_t*)&g_qh_l[obase + col] = lo;
                } else if (MODE == 1) {
                    x += vec[col]     + vec[128 + col]     * lm1 + vec[256 + col]     * l0 + vec[384 + col]     * lp1;
                    y += vec[col + 1] + vec[128 + col + 1] * lm1 + vec[256 + col + 1] * l0 + vec[384 + col + 1] * lp1;
                    uint32_t hi = pk2h(x, y);
                    *(uint32_t*)&g_vh_h[obase + col] = hi;
                    // stage transposed copy: [v=row][d=col] pitch 65 words
                    *(uint32_t*)(sm + (row * 65 + (col >> 1)) * 4) = hi;
                } else if (MODE == 2) {
                    const float sc = 0.08838834764831845f;
                    *(float2*)(dst + col) = make_float2(x * sc, y * sc);
                } else {
                    *(float2*)(dst + col) = make_float2(x, y);
                }
            }
        }
    }

    if (MODE == 1) {
        __syncthreads();
        // write g_vhT: thread t -> d = t>>1, v-half = t&1 (64 v each)
        const int b = blockIdx.y >> 4, h = blockIdx.x;
        const int vpos0 = (blockIdx.y & 15) * 128;
        const int d = t >> 1, vh2 = t & 1;
        size_t ob = (((size_t)(h * 32 + b)) * 128 + d) * VL + vpos0 + vh2 * 64;
#pragma unroll
        for (int blk = 0; blk < 8; blk++) {
            uint16_t e[8];
#pragma unroll
            for (int j = 0; j < 8; j++) {
                int v = vh2 * 64 + blk * 8 + j;
                e[j] = *(uint16_t*)(sm + (v * 65 + (d >> 1)) * 4 + (d & 1) * 2);
            }
            uint4 o;
            o.x = (uint32_t)e[0] | ((uint32_t)e[1] << 16);
            o.y = (uint32_t)e[2] | ((uint32_t)e[3] << 16);
            o.z = (uint32_t)e[4] | ((uint32_t)e[5] << 16);
            o.w = (uint32_t)e[6] | ((uint32_t)e[7] << 16);
            *(uint4*)&g_vhT_h[ob + blk * 8] = o;
        }
    }
}

// ---------------------------------------------------------------------------
// elementwise fp32 -> fp16 hi/lo split
// ---------------------------------------------------------------------------
DI void split_body(const float4* __restrict__ in, uint16_t* oh, uint16_t* ol, int n4) {
    int i = blockIdx.x * 256 + threadIdx.x;
    if (i >= n4) return;
    float4 x = in[i];
    uint32_t l0, l1;
    uint32_t h0 = sp2h(x.x, x.y, l0), h1 = sp2h(x.z, x.w, l1);
    uint2 H; H.x = h0; H.y = h1;
    *(uint2*)&oh[(size_t)i * 4] = H;
    if (ol) { uint2 L; L.x = l0; L.y = l1; *(uint2*)&ol[(size_t)i * 4] = L; }
}
__global__ void split_q_k(const float4* in)  { split_body(in, s_q_h, s_q_l, 1048576); }
__global__ void split_v_k(const float4* in)  { split_body(in, s_v_h, nullptr, 16777216); }
__global__ void split_wq_k(const float4* in) { split_body(in, s_Wq_h, nullptr, 262144); }
__global__ void split_wv_k(const float4* in) { split_body(in, s_Wv_h, nullptr, 262144); }

// ---------------------------------------------------------------------------
__global__ void prep_kernel(const float* __restrict__ conv_w,
                            const float* __restrict__ conv_b,
                            const float* __restrict__ Wloc)
{
    int d = threadIdx.x;
    float a0 = 0.f, a1 = 0.f, a2 = 0.f, c = 0.f;
#pragma unroll
    for (int cc = 0; cc < 10; cc++) {
        float wl = Wloc[d * 10 + cc];
        a0 += wl * conv_w[cc * 3 + 0];
        a1 += wl * conv_w[cc * 3 + 1];
        a2 += wl * conv_w[cc * 3 + 2];
        c  += wl * conv_b[cc];
    }
    g_A0[d] = a0; g_A1[d] = a1; g_A2[d] = a2; g_Cc[d] = c;
}

// ---------------------------------------------------------------------------
__global__ void __launch_bounds__(256) softmax_kernel(float* __restrict__ attn)
{
    __shared__ float sm1[8], sm2[8];
    const size_t base = (size_t)blockIdx.x * VL;
    const int t = threadIdx.x, lane = t & 31, w = t >> 5;
    float4 a = *(float4*)(attn + base + t * 4);
    float4 b = *(float4*)(attn + base + 1024 + t * 4);
    float m = fmaxf(fmaxf(fmaxf(a.x, a.y), fmaxf(a.z, a.w)),
                    fmaxf(fmaxf(b.x, b.y), fmaxf(b.z, b.w)));
#pragma unroll
    for (int s = 16; s; s >>= 1) m = fmaxf(m, __shfl_xor_sync(~0u, m, s));
    if (lane == 0) sm1[w] = m;
    __syncthreads();
    m = sm1[0];
#pragma unroll
    for (int i = 1; i < 8; i++) m = fmaxf(m, sm1[i]);
    a.x = __expf(a.x - m); a.y = __expf(a.y - m); a.z = __expf(a.z - m); a.w = __expf(a.w - m);
    b.x = __expf(b.x - m); b.y = __expf(b.y - m); b.z = __expf(b.z - m); b.w = __expf(b.w - m);
    float s = a.x + a.y + a.z + a.w + b.x + b.y + b.z + b.w;
#pragma unroll
    for (int sh = 16; sh; sh >>= 1) s += __shfl_xor_sync(~0u, s, sh);
    if (lane == 0) sm2[w] = s;
    __syncthreads();
    s = sm2[0];
#pragma unroll
    for (int i = 1; i < 8; i++) s += sm2[i];
    float inv = 1.0f / s;
    a.x *= inv; a.y *= inv; a.z *= inv; a.w *= inv;
    b.x *= inv; b.y *= inv; b.z *= inv; b.w *= inv;
    *(float4*)(attn + base + t * 4) = a;
    *(float4*)(attn + base + 1024 + t * 4) = b;
}

// ---------------------------------------------------------------------------
extern "C" void kernel_launch(void* const* d_in, const int* in_sizes, int n_in,
                              void* d_out, int out_size)
{
    const float* q         = (const float*)d_in[0];
    const float* v         = (const float*)d_in[1];
    const float* last_attn = (const float*)d_in[2];
    const float* conv_w    = (const float*)d_in[3];
    const float* conv_b    = (const float*)d_in[4];
    const float* Wq        = (const float*)d_in[5];
    const float* bq        = (const float*)d_in[6];
    const float* Wv        = (const float*)d_in[7];
    const float* Wloc      = (const float*)d_in[8];
    const float* bias      = (const float*)d_in[9];

    float* out  = (float*)d_out;
    float* attn = out + 4194304;

    const int SM3 = 3 * 3 * TILE_B;   // 92160 (modes 0/2/3)
    const int SM2 = 3 * 2 * TILE_B;   // 61440 (mode 1)

    static bool attr_done = false;
    if (!attr_done) {
        cudaFuncSetAttribute(mma_gemm<0>, cudaFuncAttributeMaxDynamicSharedMemorySize, SM3);
        cudaFuncSetAttribute(mma_gemm<1>, cudaFuncAttributeMaxDynamicSharedMemorySize, SM2);
        cudaFuncSetAttribute(mma_gemm<2>, cudaFuncAttributeMaxDynamicSharedMemorySize, SM3);
        cudaFuncSetAttribute(mma_gemm<3>, cudaFuncAttributeMaxDynamicSharedMemorySize, SM3);
        attr_done = true;
    }

    prep_kernel<<<1, 128>>>(conv_w, conv_b, Wloc);
    split_q_k <<<4096,  256>>>((const float4*)q);
    split_v_k <<<65536, 256>>>((const float4*)v);
    split_wq_k<<<1024,  256>>>((const float4*)Wq);
    split_wv_k<<<1024,  256>>>((const float4*)Wv);

    mma_gemm<0><<<dim3(8, 32),   256, SM3>>>(nullptr, bq,   nullptr,   nullptr);
    mma_gemm<1><<<dim3(8, 512),  256, SM2>>>(nullptr, bias, last_attn, nullptr);
    mma_gemm<2><<<dim3(16, 256), 256, SM3>>>(nullptr, nullptr, nullptr, attn);
    softmax_kernel<<<32768, 256>>>(attn);
    mma_gemm<3><<<256, 256, SM3>>>(attn, nullptr, nullptr, out);
}